// round 10
// baseline (speedup 1.0000x reference)
#include <cuda_runtime.h>
#include <math.h>

#define DIM      4096
#define BATCH    8192
#define NLAYERS  6
#define EPS      1e-12f
#define MAXNORM  10.0f

// Output layout (fp32, concatenated in reference return order):
//   h_final  : [BATCH, DIM]            offset 0
//   aligns   : [NLAYERS, BATCH, 3]     offset TRACE_A
//   divs     : [NLAYERS, BATCH, 3]     offset TRACE_D
//   tensions : [NLAYERS, BATCH, 3]     offset TRACE_T
#define TRACE_A  ((size_t)BATCH * DIM)
#define TRACE_SZ ((size_t)NLAYERS * BATCH * 3)
#define TRACE_D  (TRACE_A + TRACE_SZ)
#define TRACE_T  (TRACE_D + TRACE_SZ)

__device__ float g_D[9];     // Gram of normalized anchor dirs
__device__ float g_invn[3];  // 1/max(||anchor_k||, eps)

// ---------------------------------------------------------------------------
// Prep: anchor norms + pairwise dots -> normalized-direction Gram. One block.
// ---------------------------------------------------------------------------
__global__ void prep_kernel(const float* __restrict__ aE,
                            const float* __restrict__ aC,
                            const float* __restrict__ aN) {
    float s[6] = {0.f, 0.f, 0.f, 0.f, 0.f, 0.f};  // EE, CC, NN, EC, EN, CN
    for (int i = threadIdx.x; i < DIM; i += 256) {
        float e = aE[i], c = aC[i], n = aN[i];
        s[0] = fmaf(e, e, s[0]);
        s[1] = fmaf(c, c, s[1]);
        s[2] = fmaf(n, n, s[2]);
        s[3] = fmaf(e, c, s[3]);
        s[4] = fmaf(e, n, s[4]);
        s[5] = fmaf(c, n, s[5]);
    }
    __shared__ float red[8][6];
    int lane = threadIdx.x & 31, w = threadIdx.x >> 5;
#pragma unroll
    for (int j = 0; j < 6; j++)
#pragma unroll
        for (int off = 16; off > 0; off >>= 1)
            s[j] += __shfl_down_sync(0xFFFFFFFFu, s[j], off);
    if (lane == 0)
#pragma unroll
        for (int j = 0; j < 6; j++) red[w][j] = s[j];
    __syncthreads();
    if (threadIdx.x == 0) {
        float t[6];
#pragma unroll
        for (int j = 0; j < 6; j++) {
            float acc = 0.f;
#pragma unroll
            for (int ww = 0; ww < 8; ww++) acc += red[ww][j];
            t[j] = acc;
        }
        float iE = 1.f / fmaxf(sqrtf(t[0]), EPS);
        float iC = 1.f / fmaxf(sqrtf(t[1]), EPS);
        float iN = 1.f / fmaxf(sqrtf(t[2]), EPS);
        g_invn[0] = iE; g_invn[1] = iC; g_invn[2] = iN;
        g_D[0] = t[0] * iE * iE;
        g_D[4] = t[1] * iC * iC;
        g_D[8] = t[2] * iN * iN;
        float ec = t[3] * iE * iC, en = t[4] * iE * iN, cn = t[5] * iC * iN;
        g_D[1] = ec; g_D[3] = ec;
        g_D[2] = en; g_D[6] = en;
        g_D[5] = cn; g_D[7] = cn;
    }
}

// ---------------------------------------------------------------------------
// Main: ONE WARP PER ROW. No shared memory, no __syncthreads — every warp
// runs its row end-to-end independently, so the SM always has issueable
// warps and memory latency is hidden by warp-level parallelism.
//   pass 1: stream row + anchors, 4 fused dots, shfl-reduce.
//   recurrence: all lanes redundantly (MUFU-only chain); lane0 writes traces.
//   pass 2: re-read row (L2-resident) + anchors (L1-hot), write h_final
//           with streaming (.cs) stores to protect L2 row residency.
// ---------------------------------------------------------------------------
__global__ __launch_bounds__(256, 5) void collapse_kernel(
    const float* __restrict__ h0,
    const float* __restrict__ aE,
    const float* __restrict__ aC,
    const float* __restrict__ aN,
    float* __restrict__ out)
{
    const int warp_global = (blockIdx.x * blockDim.x + threadIdx.x) >> 5;
    const int lane        = threadIdx.x & 31;
    const int row         = warp_global;
    if (row >= BATCH) return;

    const float4* hr = (const float4*)(h0 + (size_t)row * DIM);
    const float4* e4 = (const float4*)aE;
    const float4* c4 = (const float4*)aC;
    const float4* n4 = (const float4*)aN;

    // ---- pass 1: 4 fused dot products over the row (32 warp-iters) ----
    float sH = 0.f, sE = 0.f, sC = 0.f, sN = 0.f;
#pragma unroll 4
    for (int it = 0; it < DIM / 4 / 32; it++) {
        int i = it * 32 + lane;
        float4 h = hr[i];
        float4 e = e4[i], c = c4[i], n = n4[i];
        sH = fmaf(h.x, h.x, fmaf(h.y, h.y, fmaf(h.z, h.z, fmaf(h.w, h.w, sH))));
        sE = fmaf(h.x, e.x, fmaf(h.y, e.y, fmaf(h.z, e.z, fmaf(h.w, e.w, sE))));
        sC = fmaf(h.x, c.x, fmaf(h.y, c.y, fmaf(h.z, c.z, fmaf(h.w, c.w, sC))));
        sN = fmaf(h.x, n.x, fmaf(h.y, n.y, fmaf(h.z, n.z, fmaf(h.w, n.w, sN))));
    }
#pragma unroll
    for (int off = 16; off > 0; off >>= 1) {
        sH += __shfl_down_sync(0xFFFFFFFFu, sH, off);
        sE += __shfl_down_sync(0xFFFFFFFFu, sE, off);
        sC += __shfl_down_sync(0xFFFFFFFFu, sC, off);
        sN += __shfl_down_sync(0xFFFFFFFFu, sN, off);
    }
    const float g00 = __shfl_sync(0xFFFFFFFFu, sH, 0);
    const float dE  = __shfl_sync(0xFFFFFFFFu, sE, 0);
    const float dC  = __shfl_sync(0xFFFFFFFFu, sC, 0);
    const float dN  = __shfl_sync(0xFFFFFFFFu, sN, 0);

    // ---- scalar 6-layer recurrence (all lanes redundant; MUFU-only) ----
    const float invn0 = g_invn[0], invn1 = g_invn[1], invn2 = g_invn[2];
    float g0[3] = { dE * invn0, dC * invn1, dN * invn2 };
    float D[9];
#pragma unroll
    for (int j = 0; j < 9; j++) D[j] = g_D[j];

    float c0 = 1.f;
    float cc[3] = { 0.f, 0.f, 0.f };
    const float str[3] = { 0.1f, 0.1f, 0.05f };

#pragma unroll
    for (int l = 0; l < NLAYERS; l++) {
        float hd[3];
#pragma unroll
        for (int k = 0; k < 3; k++)
            hd[k] = c0 * g0[k] + cc[0] * D[0 * 3 + k] + cc[1] * D[1 * 3 + k] + cc[2] * D[2 * 3 + k];
        float hh = c0 * (c0 * g00 + cc[0] * g0[0] + cc[1] * g0[1] + cc[2] * g0[2])
                 + cc[0] * hd[0] + cc[1] * hd[1] + cc[2] * hd[2];
        float inv = rsqrtf(fmaxf(hh, 1e-24f));   // 1/||h||

        float a[3];
#pragma unroll
        for (int k = 0; k < 3; k++) {
            float align = hd[k] * inv;
            float dv    = 1.f - align;
            float tens  = fmaxf(dv, 0.f);
            if (lane == 0) {
                size_t ti = (size_t)l * (BATCH * 3) + (size_t)row * 3 + k;
                __stcs(out + TRACE_A + ti, align);
                __stcs(out + TRACE_D + ti, dv);
                __stcs(out + TRACE_T + ti, tens);
            }
            float msq = fmaxf(hh - 2.f * hd[k] + D[k * 3 + k], 1e-24f);
            a[k] = str[k] * dv * rsqrtf(msq);    // str*dv/||h - dir_k||
        }
        float f = 1.f - (a[0] + a[1] + a[2]);
        c0 *= f;
        cc[0] = cc[0] * f + a[0];
        cc[1] = cc[1] * f + a[1];
        cc[2] = cc[2] * f + a[2];

        // ||h_new|| via Gram quadratic form; clamp to MAXNORM
        float hd2[3];
#pragma unroll
        for (int k = 0; k < 3; k++)
            hd2[k] = c0 * g0[k] + cc[0] * D[0 * 3 + k] + cc[1] * D[1 * 3 + k] + cc[2] * D[2 * 3 + k];
        float hh2 = c0 * (c0 * g00 + cc[0] * g0[0] + cc[1] * g0[1] + cc[2] * g0[2])
                  + cc[0] * hd2[0] + cc[1] * hd2[1] + cc[2] * hd2[2];
        float rn = rsqrtf(fmaxf(hh2, 1e-24f));
        float nn = hh2 * rn;                     // ||h_new||
        if (nn > MAXNORM) {
            float scl = MAXNORM * rn;            // 10/||h||
            c0 *= scl; cc[0] *= scl; cc[1] *= scl; cc[2] *= scl;
        }
    }
    const float wE = cc[0] * invn0, wC = cc[1] * invn1, wN = cc[2] * invn2;

    // ---- pass 2: h_final = c0*h + wE*E + wC*C + wN*N (row re-read, L2-hot) ----
    float4* orow = (float4*)(out + (size_t)row * DIM);
#pragma unroll 4
    for (int it = 0; it < DIM / 4 / 32; it++) {
        int i = it * 32 + lane;
        float4 h = hr[i];
        float4 e = e4[i], c = c4[i], n = n4[i];
        float4 o;
        o.x = fmaf(c0, h.x, fmaf(wE, e.x, fmaf(wC, c.x, wN * n.x)));
        o.y = fmaf(c0, h.y, fmaf(wE, e.y, fmaf(wC, c.y, wN * n.y)));
        o.z = fmaf(c0, h.z, fmaf(wE, e.z, fmaf(wC, c.z, wN * n.z)));
        o.w = fmaf(c0, h.w, fmaf(wE, e.w, fmaf(wC, c.w, wN * n.w)));
        __stcs((float4*)&orow[i], o);
    }
}

extern "C" void kernel_launch(void* const* d_in, const int* in_sizes, int n_in,
                              void* d_out, int out_size) {
    const float* h0 = (const float*)d_in[0];
    const float* aE = (const float*)d_in[1];
    const float* aC = (const float*)d_in[2];
    const float* aN = (const float*)d_in[3];
    float* out = (float*)d_out;

    prep_kernel<<<1, 256>>>(aE, aC, aN);
    // one warp per row: 8192 warps = 1024 blocks of 256 threads
    collapse_kernel<<<BATCH / 8, 256>>>(h0, aE, aC, aN, out);
}